// round 15
// baseline (speedup 1.0000x reference)
#include <cuda_runtime.h>

#define BS 8192
#define C 23
#define F 1024
#define CF (C * F)         /* 23552 */
#define CF4 (CF / 4)       /* 5888  */
#define NCHUNK 16
#define ROWS (BS / NCHUNK) /* 512 rows per chunk */
#define TPC 16             /* 32-row tiles per chunk (512/32) */
#define PPC 8              /* tile-pairs per chunk */
#define EPS 1e-5f

// Scratch (__device__ globals; no allocations allowed)
__device__ float g_partial[(size_t)NCHUNK * 2 * CF]; // [chunk][{sum,sumsq}][CF] ~3 MB
__device__ float g_s[CF];        // fused per-(c,f) scale: rsqrt(var1+eps)*gamma1*W1
__device__ float g_h[C * BS];    // h TRANSPOSED: [c][b]
__device__ float g_mean2[C];
__device__ float g_k2[C];        // rsqrt(var2+eps)*gamma2*W2

// ---------------------------------------------------------------------------
// k1: per-(c,f) partial sums of x and x^2 over a 512-row batch chunk.
// grid (23, 16), block 256 — all 368 blocks chip-resident, finish together.
// Uniform evict-normal loads: L2 keeps the stream tail for k3 to harvest.
// ---------------------------------------------------------------------------
__global__ void k1_colsums(const float* __restrict__ x) {
    int cf4 = blockIdx.x * 256 + threadIdx.x;   // 0..5887
    int chunk = blockIdx.y;                     // 0..15
    const float4* xp = (const float4*)x;
    long base = (long)chunk * ROWS * CF4 + cf4;

    float4 s = make_float4(0.f, 0.f, 0.f, 0.f);
    float4 q = make_float4(0.f, 0.f, 0.f, 0.f);
#pragma unroll 8
    for (int r = 0; r < ROWS; r++) {
        float4 v = __ldg(&xp[base + (long)r * CF4]);
        s.x += v.x; s.y += v.y; s.z += v.z; s.w += v.w;
        q.x += v.x * v.x; q.y += v.y * v.y; q.z += v.z * v.z; q.w += v.w * v.w;
    }
    ((float4*)g_partial)[(long)chunk * 2 * CF4 + cf4] = s;
    ((float4*)g_partial)[(long)chunk * 2 * CF4 + CF4 + cf4] = q;
}

// ---------------------------------------------------------------------------
// k2: fold NCHUNK partials -> s[c,f] = rsqrt(var1+eps) * gamma1 * W1
// grid 92, block 256. PDL: gamma/W prefetch pre-sync (harness inputs only).
// ---------------------------------------------------------------------------
__global__ void k2_scale(const float* __restrict__ gamma1,
                         const float* __restrict__ W1) {
    int cf = blockIdx.x * 256 + threadIdx.x;
    float g = gamma1[cf];                 // independent of k1 — prefetch pre-sync
    float w = W1[cf];
    cudaGridDependencySynchronize();      // wait for k1's g_partial
    float s = 0.f, q = 0.f;
#pragma unroll
    for (int k = 0; k < NCHUNK; k++) {
        s += g_partial[(long)k * 2 * CF + cf];
        q += g_partial[(long)k * 2 * CF + CF + cf];
    }
    float mean = s * (1.0f / BS);
    float var  = q * (1.0f / BS) - mean * mean;
    g_s[cf] = rsqrtf(var + EPS) * g * w;
}

// ---------------------------------------------------------------------------
// k3: h[c][b] = dot(x[b,c,:], s[c,:]).  Block = one channel c + a PAIR of
// adjacent 32-row tiles (64 rows): one g_s staging serves both tiles, halving
// s-staging L2 traffic and block prologues vs one-tile blocks.
// Pair schedule reversed per chunk (pair 7 = rows 448..511 first) to harvest
// k1's L2 residue; within a pair the hotter tile (t=1) is processed first.
// PDL: ALL loads stay behind the gate (R13 lesson: pre-gate x reads steal
// stream bandwidth from k1). grid 23*128 = 2944, block 256.
// ---------------------------------------------------------------------------
__global__ void k3_dot(const float* __restrict__ x) {
    __shared__ float4 ss[256];
    int c = blockIdx.x % C;
    int l = blockIdx.x / C;                     // launch-order pair index 0..127
    int prank = l >> 4;                         // 0..7 (0 = hottest)
    int chunk = l & 15;                         // 0..15
    int btile0 = chunk * TPC + (PPC - 1 - prank) * 2; // first tile of the pair
    int w = threadIdx.x >> 5, lane = threadIdx.x & 31;

    cudaGridDependencySynchronize();            // wait for k2's g_s
    ss[threadIdx.x] = ((const float4*)g_s)[c * 256 + threadIdx.x];
    __syncthreads();

#pragma unroll
    for (int t = 1; t >= 0; t--) {              // hotter tile first
        int b0 = (btile0 + t) * 32 + w * 4;
        float acc[4];
#pragma unroll
        for (int j = 0; j < 4; j++) {
            const float4* xp = (const float4*)x + ((long)(b0 + j) * C + c) * 256;
            float a = 0.f;
#pragma unroll
            for (int i = 0; i < 8; i++) {
                float4 v  = __ldcs(&xp[lane + 32 * i]);   // no further reuse
                float4 wv = ss[lane + 32 * i];
                a += v.x * wv.x; a += v.y * wv.y;
                a += v.z * wv.z; a += v.w * wv.w;
            }
            acc[j] = a;
        }
#pragma unroll
        for (int o = 16; o; o >>= 1) {
#pragma unroll
            for (int j = 0; j < 4; j++)
                acc[j] += __shfl_xor_sync(0xffffffffu, acc[j], o);
        }
        if (lane == 0) {
            *(float4*)(&g_h[c * BS + b0]) =
                make_float4(acc[0], acc[1], acc[2], acc[3]);
        }
    }
}

// ---------------------------------------------------------------------------
// k4: BatchNorm1d(23) batch stats over h[c][:] (contiguous, coalesced).
// grid 23, block 1024. PDL: sync before reading g_h.
// ---------------------------------------------------------------------------
__global__ void k4_stats(const float* __restrict__ gamma2,
                         const float* __restrict__ W2) {
    __shared__ float sh_s[32], sh_q[32];
    int c = blockIdx.x;
    int t = threadIdx.x, lane = t & 31, w = t >> 5;

    cudaGridDependencySynchronize();            // wait for k3's g_h
    const float4* hp = (const float4*)(&g_h[c * BS]);
    float s = 0.f, q = 0.f;
#pragma unroll
    for (int i = 0; i < 2; i++) {
        float4 v = hp[t + 1024 * i];
        s += v.x + v.y + v.z + v.w;
        q += v.x * v.x + v.y * v.y + v.z * v.z + v.w * v.w;
    }
#pragma unroll
    for (int o = 16; o; o >>= 1) {
        s += __shfl_xor_sync(0xffffffffu, s, o);
        q += __shfl_xor_sync(0xffffffffu, q, o);
    }
    if (lane == 0) { sh_s[w] = s; sh_q[w] = q; }
    __syncthreads();
    if (w == 0) {
        s = sh_s[lane]; q = sh_q[lane];
#pragma unroll
        for (int o = 16; o; o >>= 1) {
            s += __shfl_xor_sync(0xffffffffu, s, o);
            q += __shfl_xor_sync(0xffffffffu, q, o);
        }
        if (lane == 0) {
            float mean = s * (1.0f / BS);
            float var  = q * (1.0f / BS) - mean * mean;
            g_mean2[c] = mean;
            g_k2[c]    = rsqrtf(var + EPS) * gamma2[c] * W2[c];
        }
    }
}

// ---------------------------------------------------------------------------
// k5: out[b] = sum_c (h[c][b]-mean2[c])*k2[c] + (sum_c beta2*W2 + b2)
// grid 32, block 256. off-term computed pre-sync (true epilogue overlap).
// ---------------------------------------------------------------------------
__global__ void k5_out(const float* __restrict__ beta2,
                       const float* __restrict__ W2,
                       const float* __restrict__ b2,
                       float* __restrict__ out) {
    int b = blockIdx.x * 256 + threadIdx.x;
    float off = b2[0];
#pragma unroll
    for (int c = 0; c < C; c++) off += beta2[c] * W2[c];

    cudaGridDependencySynchronize();            // wait for k4 (=> k3 done too)
    float a = 0.f;
#pragma unroll
    for (int c = 0; c < C; c++)
        a += (g_h[c * BS + b] - g_mean2[c]) * g_k2[c];
    out[b] = a + off;
}

// ---------------------------------------------------------------------------
// PDL launch helper: programmatic stream serialization lets the next grid
// launch while the previous one drains; device-side sync guards the data.
// ---------------------------------------------------------------------------
template <typename K, typename... Args>
static void launch_pdl(dim3 grid, dim3 block, K kernel, Args... args) {
    cudaLaunchConfig_t cfg = {};
    cudaLaunchAttribute attr[1];
    attr[0].id = cudaLaunchAttributeProgrammaticStreamSerialization;
    attr[0].val.programmaticStreamSerializationAllowed = 1;
    cfg.gridDim = grid;
    cfg.blockDim = block;
    cfg.dynamicSmemBytes = 0;
    cfg.stream = 0;
    cfg.attrs = attr;
    cfg.numAttrs = 1;
    cudaLaunchKernelEx(&cfg, kernel, args...);
}

extern "C" void kernel_launch(void* const* d_in, const int* in_sizes, int n_in,
                              void* d_out, int out_size) {
    const float* x      = (const float*)d_in[0];
    const float* gamma1 = (const float*)d_in[1];
    /* beta1 = d_in[2], b1 = d_in[4]: algebraically cancelled by BatchNorm1d(23) */
    const float* W1     = (const float*)d_in[3];
    const float* gamma2 = (const float*)d_in[5];
    const float* beta2  = (const float*)d_in[6];
    const float* W2     = (const float*)d_in[7];
    const float* b2     = (const float*)d_in[8];
    float* out = (float*)d_out;

    k1_colsums<<<dim3(23, NCHUNK), 256>>>(x);
    launch_pdl(dim3(CF / 256), dim3(256), k2_scale, gamma1, W1);
    launch_pdl(dim3(C * (BS / 64)), dim3(256), k3_dot, x);
    launch_pdl(dim3(C), dim3(1024), k4_stats, gamma2, W2);
    launch_pdl(dim3(BS / 256), dim3(256), k5_out, beta2, W2, b2, out);
}

// round 16
// speedup vs baseline: 1.0289x; 1.0289x over previous
#include <cuda_runtime.h>

#define BS 8192
#define C 23
#define F 1024
#define CF (C * F)         /* 23552 */
#define CF4 (CF / 4)       /* 5888  */
#define NCHUNK 16
#define ROWS (BS / NCHUNK) /* 512 rows per chunk */
#define TPC 16             /* 32-row tiles per chunk (512/32) */
#define EPS 1e-5f

// Scratch (__device__ globals; no allocations allowed)
__device__ float g_partial[(size_t)NCHUNK * 2 * CF]; // [chunk][{sum,sumsq}][CF] ~3 MB
__device__ float g_s[CF];        // fused per-(c,f) scale: rsqrt(var1+eps)*gamma1*W1
__device__ float g_h[C * BS];    // h TRANSPOSED: [c][b]
__device__ float g_mean2[C];
__device__ float g_k2[C];        // rsqrt(var2+eps)*gamma2*W2

// ---------------------------------------------------------------------------
// k1: per-(c,f) partial sums of x and x^2 over a 512-row batch chunk.
// grid (23, 16), block 256 — all 368 blocks chip-resident, finish together.
// Uniform evict-normal loads: L2 keeps the stream tail for k3 to harvest.
// ---------------------------------------------------------------------------
__global__ void k1_colsums(const float* __restrict__ x) {
    int cf4 = blockIdx.x * 256 + threadIdx.x;   // 0..5887
    int chunk = blockIdx.y;                     // 0..15
    const float4* xp = (const float4*)x;
    long base = (long)chunk * ROWS * CF4 + cf4;

    float4 s = make_float4(0.f, 0.f, 0.f, 0.f);
    float4 q = make_float4(0.f, 0.f, 0.f, 0.f);
#pragma unroll 8
    for (int r = 0; r < ROWS; r++) {
        float4 v = __ldg(&xp[base + (long)r * CF4]);
        s.x += v.x; s.y += v.y; s.z += v.z; s.w += v.w;
        q.x += v.x * v.x; q.y += v.y * v.y; q.z += v.z * v.z; q.w += v.w * v.w;
    }
    ((float4*)g_partial)[(long)chunk * 2 * CF4 + cf4] = s;
    ((float4*)g_partial)[(long)chunk * 2 * CF4 + CF4 + cf4] = q;
}

// ---------------------------------------------------------------------------
// k2: fold NCHUNK partials -> s[c,f] = rsqrt(var1+eps) * gamma1 * W1
// grid 92, block 256. PDL: gamma/W prefetch pre-sync (harness inputs only).
// ---------------------------------------------------------------------------
__global__ void k2_scale(const float* __restrict__ gamma1,
                         const float* __restrict__ W1) {
    int cf = blockIdx.x * 256 + threadIdx.x;
    float g = gamma1[cf];                 // independent of k1 — prefetch pre-sync
    float w = W1[cf];
    cudaGridDependencySynchronize();      // wait for k1's g_partial
    float s = 0.f, q = 0.f;
#pragma unroll
    for (int k = 0; k < NCHUNK; k++) {
        s += g_partial[(long)k * 2 * CF + cf];
        q += g_partial[(long)k * 2 * CF + CF + cf];
    }
    float mean = s * (1.0f / BS);
    float var  = q * (1.0f / BS) - mean * mean;
    g_s[cf] = rsqrtf(var + EPS) * g * w;
}

// ---------------------------------------------------------------------------
// k3: h[c][b] = dot(x[b,c,:], s[c,:]).  Block = one channel c + 32 batch rows.
// Batch-tile schedule reversed per chunk to harvest k1's L2 residue: early
// blocks take the tail tiles of every chunk (most recently streamed rows),
// walking toward the cold head rows. One tile per block (grid 5888) keeps the
// wave-1 footprint aligned with the residue (R15 lesson: pairing breaks it).
// PDL: ALL loads (x included) stay behind the gate (R13 lesson: pre-gate x
// reads steal stream bandwidth from k1's critical path).
// grid 23*256 = 5888, block 256.
// ---------------------------------------------------------------------------
__global__ void k3_dot(const float* __restrict__ x) {
    __shared__ float4 ss[256];
    int c = blockIdx.x % C;
    int l = blockIdx.x / C;                     // launch-order tile index 0..255
    int rank  = l >> 4;                         // 0..15 (0 = hottest)
    int chunk = l & 15;                         // 0..15
    int btile = chunk * TPC + (TPC - 1 - rank); // actual 32-row tile
    int w = threadIdx.x >> 5, lane = threadIdx.x & 31;
    int b0 = btile * 32 + w * 4;

    cudaGridDependencySynchronize();            // wait for k2's g_s
    ss[threadIdx.x] = ((const float4*)g_s)[c * 256 + threadIdx.x];
    __syncthreads();

    float acc[4];
#pragma unroll
    for (int j = 0; j < 4; j++) {
        const float4* xp = (const float4*)x + ((long)(b0 + j) * C + c) * 256;
        float a = 0.f;
#pragma unroll
        for (int i = 0; i < 8; i++) {
            float4 v  = __ldcs(&xp[lane + 32 * i]);   // no further reuse
            float4 wv = ss[lane + 32 * i];
            a += v.x * wv.x; a += v.y * wv.y;
            a += v.z * wv.z; a += v.w * wv.w;
        }
        acc[j] = a;
    }
#pragma unroll
    for (int o = 16; o; o >>= 1) {
#pragma unroll
        for (int j = 0; j < 4; j++)
            acc[j] += __shfl_xor_sync(0xffffffffu, acc[j], o);
    }
    if (lane == 0) {
        // transposed store: h[c][b0..b0+3] -> one STG.128
        *(float4*)(&g_h[c * BS + b0]) =
            make_float4(acc[0], acc[1], acc[2], acc[3]);
    }
}

// ---------------------------------------------------------------------------
// k4: BatchNorm1d(23) batch stats over h[c][:] (contiguous, coalesced).
// grid 23, block 1024. PDL: sync before reading g_h.
// ---------------------------------------------------------------------------
__global__ void k4_stats(const float* __restrict__ gamma2,
                         const float* __restrict__ W2) {
    __shared__ float sh_s[32], sh_q[32];
    int c = blockIdx.x;
    int t = threadIdx.x, lane = t & 31, w = t >> 5;

    cudaGridDependencySynchronize();            // wait for k3's g_h
    const float4* hp = (const float4*)(&g_h[c * BS]);
    float s = 0.f, q = 0.f;
#pragma unroll
    for (int i = 0; i < 2; i++) {
        float4 v = hp[t + 1024 * i];
        s += v.x + v.y + v.z + v.w;
        q += v.x * v.x + v.y * v.y + v.z * v.z + v.w * v.w;
    }
#pragma unroll
    for (int o = 16; o; o >>= 1) {
        s += __shfl_xor_sync(0xffffffffu, s, o);
        q += __shfl_xor_sync(0xffffffffu, q, o);
    }
    if (lane == 0) { sh_s[w] = s; sh_q[w] = q; }
    __syncthreads();
    if (w == 0) {
        s = sh_s[lane]; q = sh_q[lane];
#pragma unroll
        for (int o = 16; o; o >>= 1) {
            s += __shfl_xor_sync(0xffffffffu, s, o);
            q += __shfl_xor_sync(0xffffffffu, q, o);
        }
        if (lane == 0) {
            float mean = s * (1.0f / BS);
            float var  = q * (1.0f / BS) - mean * mean;
            g_mean2[c] = mean;
            g_k2[c]    = rsqrtf(var + EPS) * gamma2[c] * W2[c];
        }
    }
}

// ---------------------------------------------------------------------------
// k5: out[b] = sum_c (h[c][b]-mean2[c])*k2[c] + (sum_c beta2*W2 + b2)
// grid 32, block 256. off-term computed pre-sync (true epilogue overlap).
// ---------------------------------------------------------------------------
__global__ void k5_out(const float* __restrict__ beta2,
                       const float* __restrict__ W2,
                       const float* __restrict__ b2,
                       float* __restrict__ out) {
    int b = blockIdx.x * 256 + threadIdx.x;
    float off = b2[0];
#pragma unroll
    for (int c = 0; c < C; c++) off += beta2[c] * W2[c];

    cudaGridDependencySynchronize();            // wait for k4 (=> k3 done too)
    float a = 0.f;
#pragma unroll
    for (int c = 0; c < C; c++)
        a += (g_h[c * BS + b] - g_mean2[c]) * g_k2[c];
    out[b] = a + off;
}

// ---------------------------------------------------------------------------
// PDL launch helper: programmatic stream serialization lets the next grid
// launch while the previous one drains; device-side sync guards the data.
// ---------------------------------------------------------------------------
template <typename K, typename... Args>
static void launch_pdl(dim3 grid, dim3 block, K kernel, Args... args) {
    cudaLaunchConfig_t cfg = {};
    cudaLaunchAttribute attr[1];
    attr[0].id = cudaLaunchAttributeProgrammaticStreamSerialization;
    attr[0].val.programmaticStreamSerializationAllowed = 1;
    cfg.gridDim = grid;
    cfg.blockDim = block;
    cfg.dynamicSmemBytes = 0;
    cfg.stream = 0;
    cfg.attrs = attr;
    cfg.numAttrs = 1;
    cudaLaunchKernelEx(&cfg, kernel, args...);
}

extern "C" void kernel_launch(void* const* d_in, const int* in_sizes, int n_in,
                              void* d_out, int out_size) {
    const float* x      = (const float*)d_in[0];
    const float* gamma1 = (const float*)d_in[1];
    /* beta1 = d_in[2], b1 = d_in[4]: algebraically cancelled by BatchNorm1d(23) */
    const float* W1     = (const float*)d_in[3];
    const float* gamma2 = (const float*)d_in[5];
    const float* beta2  = (const float*)d_in[6];
    const float* W2     = (const float*)d_in[7];
    const float* b2     = (const float*)d_in[8];
    float* out = (float*)d_out;

    k1_colsums<<<dim3(23, NCHUNK), 256>>>(x);
    launch_pdl(dim3(CF / 256), dim3(256), k2_scale, gamma1, W1);
    launch_pdl(dim3(C * (BS / 32)), dim3(256), k3_dot, x);
    launch_pdl(dim3(C), dim3(1024), k4_stats, gamma2, W2);
    launch_pdl(dim3(BS / 256), dim3(256), k5_out, beta2, W2, b2, out);
}